// round 6
// baseline (speedup 1.0000x reference)
#include <cuda_runtime.h>
#include <cuda_fp16.h>
#include <cstdint>

#define N_NODES   131072
#define NUM_LAYERS 4
#define NUM_EQ    1024
#define NUM_TILES 1024
#define SCALE 64.0f

// smem: [0..2048) neighbor ids, [4096 ..) 2 x 32KB stage bufs (A 16K | B 16K)
#define SMEM_BYTES (4096 + 2 * 32768)

// ---------------- static device buffers (no allocs allowed) ----------------
__device__ __align__(16) __half g_f0[N_NODES * 128];
__device__ __align__(16) __half g_f1[N_NODES * 128];
// weight blobs: [layer][sub 0..9][128 n-rows x 64 k fp16, ldsm-swizzled]
// sub 0..7 -> W0 K-chunks (K=512), sub 8..9 -> W1 K-chunks (K=128)
__device__ __align__(16) __half g_wblob[NUM_LAYERS * 10 * 8192];

// ---------------- helpers ----------------
__device__ __forceinline__ uint32_t smem_u32(const void* p) {
    uint32_t a;
    asm("{ .reg .u64 t; cvta.to.shared.u64 t, %1; cvt.u32.u64 %0, t; }"
        : "=r"(a) : "l"(p));
    return a;
}
#define CP16(dst, src, sz) \
    asm volatile("cp.async.cg.shared.global [%0], [%1], 16, %2;" \
                 :: "r"(dst), "l"(src), "r"(sz) : "memory")
#define CPCOMMIT() asm volatile("cp.async.commit_group;" ::: "memory")
#define CPWAIT0()  asm volatile("cp.async.wait_group 0;" ::: "memory")

__device__ __forceinline__ void ldsm4(uint32_t* r, uint32_t addr) {
    asm volatile("ldmatrix.sync.aligned.m8n8.x4.shared.b16 {%0,%1,%2,%3}, [%4];"
                 : "=r"(r[0]), "=r"(r[1]), "=r"(r[2]), "=r"(r[3]) : "r"(addr));
}
__device__ __forceinline__ void hmma(float* d, const uint32_t* a,
                                     uint32_t b0, uint32_t b1) {
    asm volatile(
        "mma.sync.aligned.m16n8k16.row.col.f32.f16.f16.f32 "
        "{%0,%1,%2,%3}, {%4,%5,%6,%7}, {%8,%9}, {%0,%1,%2,%3};"
        : "+f"(d[0]), "+f"(d[1]), "+f"(d[2]), "+f"(d[3])
        : "r"(a[0]), "r"(a[1]), "r"(a[2]), "r"(a[3]), "r"(b0), "r"(b1));
}
// tile: 128 rows x 64 k fp16 (128B rows, 8x16B chunks), XOR swizzle for ldsm
__device__ __forceinline__ uint32_t tadr(uint32_t base, int row, int ck) {
    return base + row * 128 + (((uint32_t)ck ^ (row & 7)) << 4);
}

// ---------------------------------------------------------------------------
// prep: transposed, ldsm-swizzled fp16 weight blobs
// ---------------------------------------------------------------------------
__global__ void prep_w(const float* __restrict__ W0, const float* __restrict__ W1) {
    int i = blockIdx.x * blockDim.x + threadIdx.x;
    if (i >= NUM_LAYERS * 10 * 8192) return;
    int e   = i & 8191;           // element within 8192-elem blob
    int g   = i >> 13;            // l*10 + sub
    int sub = g % 10;
    int l   = g / 10;
    int n   = e >> 6;             // N row 0..127
    int kk  = e & 63;             // K within subtile
    float w;
    if (sub < 8) w = W0[((size_t)l * 512 + sub * 64 + kk) * 128 + n];
    else         w = W1[((size_t)l * 128 + (sub - 8) * 64 + kk) * 128 + n];
    int ck = kk >> 3;
    uint32_t sw = (uint32_t)(n * 128) + (((uint32_t)ck ^ (n & 7)) << 4) + (kk & 7) * 2;
    *reinterpret_cast<__half*>(
        reinterpret_cast<char*>(g_wblob) + (size_t)(i - e) * 2 + sw) = __float2half_rn(w);
}

// ---------------------------------------------------------------------------
// embed: feats = SCALE * emb[node_idx]  -> fp16 into buffer 0
// ---------------------------------------------------------------------------
__global__ void embed_k(const int* __restrict__ node_idx, const float* __restrict__ emb) {
    int i = blockIdx.x * blockDim.x + threadIdx.x;   // one per 4 elems
    if (i >= N_NODES * 32) return;
    int n  = i >> 5;
    int c4 = i & 31;
    float4 vv = reinterpret_cast<const float4*>(emb)[node_idx[n] * 32 + c4];
    __half2 p0 = __floats2half2_rn(vv.x * SCALE, vv.y * SCALE);
    __half2 p1 = __floats2half2_rn(vv.z * SCALE, vv.w * SCALE);
    reinterpret_cast<uint2*>(g_f0)[i] =
        make_uint2(*reinterpret_cast<uint32_t*>(&p0), *reinterpret_cast<uint32_t*>(&p1));
}

// ---------------------------------------------------------------------------
// fused layer: plain fp16 HMMA, ring-2, 3 CTAs/SM
// XOR addressing: ldsm addr = lane_base ^ (csel<<4); bits 4-6 form the
// swizzle field, untouched by the row*128 / +2048 terms.
// ---------------------------------------------------------------------------
__device__ __forceinline__ void compute64(float acc[2][8][4], uint32_t buf,
                                          int lane, int wy, int wx) {
    const int rsel = lane & 15;
    const int hi   = lane >> 4;
    const uint32_t abase = buf + (wy * 32 + rsel) * 128 + ((rsel & 7) << 4);
    const uint32_t bbase = buf + 16384 + (wx * 64 + rsel) * 128 + ((rsel & 7) << 4);
    #pragma unroll
    for (int ks = 0; ks < 4; ks++) {
        const uint32_t xo = (uint32_t)(2 * ks + hi) << 4;
        uint32_t a[2][4];
        #pragma unroll
        for (int mi = 0; mi < 2; mi++)
            ldsm4(a[mi], (abase + mi * 2048) ^ xo);
        #pragma unroll
        for (int g = 0; g < 4; g++) {
            uint32_t b[4];
            ldsm4(b, (bbase + g * 2048) ^ xo);
            #pragma unroll
            for (int mi = 0; mi < 2; mi++) {
                hmma(acc[mi][2 * g],     a[mi], b[0], b[2]);
                hmma(acc[mi][2 * g + 1], a[mi], b[1], b[3]);
            }
        }
    }
}

__global__ __launch_bounds__(256, 3)
void layer_k(int l, int srcBuf, const int* __restrict__ neighbors,
             const float* __restrict__ b0, const float* __restrict__ b1) {
    extern __shared__ __align__(16) char smem[];
    int* sNbr = (int*)smem;
    const uint32_t sb = smem_u32(smem);
    const uint32_t BUF0 = sb + 4096, BUF1 = BUF0 + 32768;

    const int tid = threadIdx.x, lane = tid & 31, wid = tid >> 5;
    const int wy = wid >> 1, wx = wid & 1;

    const __half* fin = srcBuf ? g_f1 : g_f0;
    __half* fout      = srcBuf ? g_f0 : g_f1;

    sNbr[tid]       = neighbors[blockIdx.x * 512 + tid];
    sNbr[tid + 256] = neighbors[blockIdx.x * 512 + 256 + tid];
    __syncthreads();

    const char* finB  = reinterpret_cast<const char*>(fin);
    const char* blobB = reinterpret_cast<const char*>(g_wblob);

    // one K=64 stage: A gather (zfill for pad node) + B blob copy
    auto issue = [&](int s) {
        const uint32_t buf = (s & 1) ? BUF1 : BUF0;
        const int j = s >> 1, half = s & 1;
        const size_t blobOff = (size_t)(l * 10 + s) * 16384;
        #pragma unroll
        for (int r = 0; r < 4; r++) {
            int c = tid + 256 * r;                 // 0..1023
            int row = c >> 3, ck = c & 7;
            int sn = sNbr[row * 4 + j];
            uint32_t sz = (sn == N_NODES) ? 0u : 16u;
            size_t so = (size_t)sn * 256 + half * 128 + ck * 16;
            CP16(tadr(buf, row, ck), finB + so, sz);
            CP16(buf + 16384 + c * 16, blobB + blobOff + c * 16, 16u);
        }
    };

    float acc[2][8][4];
    #pragma unroll
    for (int mi = 0; mi < 2; mi++)
        #pragma unroll
        for (int ni = 0; ni < 8; ni++)
            #pragma unroll
            for (int q = 0; q < 4; q++) acc[mi][ni][q] = 0.f;

    // -------- GEMM1: gathered[128x512] @ W0, 8 K=64 stages, ring-2 --------
    issue(0); CPCOMMIT();
    #pragma unroll 1
    for (int s = 0; s < 8; s++) {
        CPWAIT0();
        __syncthreads();                 // stage s data visible to all;
                                         // all warps also done with compute(s-1)
        if (s < 7) { issue(s + 1); CPCOMMIT(); }   // writes the other buffer
        compute64(acc, (s & 1) ? BUF1 : BUF0, lane, wy, wx);
    }
    __syncthreads();                     // all warps done reading buf0/buf1

    // -------- epilogue1: W1 prefetch + H = relu(acc + s*b0) -> fp16 A tiles ----
    #pragma unroll
    for (int r = 0; r < 8; r++) {
        int idx = tid + 256 * r;                   // 0..2047
        int region = idx >> 10;                    // 0: W1 sub8 -> buf0.B, 1: sub9 -> buf1.B
        int c = idx & 1023;
        uint32_t dst = (region ? BUF1 : BUF0) + 16384 + c * 16;
        size_t src = (size_t)(l * 10 + 8 + region) * 16384 + (size_t)c * 16;
        CP16(dst, blobB + src, 16u);
    }
    CPCOMMIT();

    const uint32_t hbuf = wx ? BUF1 : BUF0;        // wx=0 -> k 0..63, wx=1 -> 64..127
    #pragma unroll
    for (int mi = 0; mi < 2; mi++) {
        #pragma unroll
        for (int ni = 0; ni < 8; ni++) {
            int kl = ni * 8 + (lane & 3) * 2;      // k within GEMM2 subtile
            int ncol = wx * 64 + kl;               // GEMM1 output column
            float bb0 = __ldg(&b0[ncol]) * SCALE;
            float bb1 = __ldg(&b0[ncol + 1]) * SCALE;
            #pragma unroll
            for (int h = 0; h < 2; h++) {          // row halves
                int row = wy * 32 + mi * 16 + (lane >> 2) + h * 8;
                float x0 = acc[mi][ni][2 * h]     + bb0;
                float x1 = acc[mi][ni][2 * h + 1] + bb1;
                x0 = x0 > 0.f ? x0 : 0.f;
                x1 = x1 > 0.f ? x1 : 0.f;
                __half2 p = __floats2half2_rn(x0, x1);
                uint32_t a = tadr(hbuf, row, kl >> 3) + (kl & 7) * 2;
                asm volatile("st.shared.b32 [%0], %1;"
                             :: "r"(a), "r"(*reinterpret_cast<uint32_t*>(&p)) : "memory");
            }
        }
    }
    CPWAIT0();
    __syncthreads();

    // -------- GEMM2: H[128x128] @ W1, 2 K=64 stages --------
    #pragma unroll
    for (int mi = 0; mi < 2; mi++)
        #pragma unroll
        for (int ni = 0; ni < 8; ni++)
            #pragma unroll
            for (int q = 0; q < 4; q++) acc[mi][ni][q] = 0.f;
    compute64(acc, BUF0, lane, wy, wx);
    compute64(acc, BUF1, lane, wy, wx);

    // -------- epilogue2: out = acc + s*b1 -> fp16 to global --------
    #pragma unroll
    for (int mi = 0; mi < 2; mi++) {
        #pragma unroll
        for (int ni = 0; ni < 8; ni++) {
            int ncol = wx * 64 + ni * 8 + (lane & 3) * 2;
            float bb0 = __ldg(&b1[ncol]) * SCALE;
            float bb1 = __ldg(&b1[ncol + 1]) * SCALE;
            #pragma unroll
            for (int h = 0; h < 2; h++) {
                int row = wy * 32 + mi * 16 + (lane >> 2) + h * 8;
                size_t gOff = (size_t)(blockIdx.x * 128 + row) * 128 + ncol;
                __half2 p = __floats2half2_rn(acc[mi][ni][2 * h] + bb0,
                                              acc[mi][ni][2 * h + 1] + bb1);
                *reinterpret_cast<uint32_t*>(fout + gOff) =
                    *reinterpret_cast<uint32_t*>(&p);
            }
        }
    }
}

// ---------------------------------------------------------------------------
// readout: logits[b] = dot(meanL, meanR)/s^2 + out_bias  (feats in g_f0)
// ---------------------------------------------------------------------------
__global__ void readout_k(const float* __restrict__ out_bias, float* __restrict__ logits) {
    const int b = blockIdx.x;
    const int t = threadIdx.x;   // 0..127
    size_t baseL = (size_t)(2 * b) * 64 * 128;
    size_t baseR = baseL + 64 * 128;
    float sl = 0.f, sr = 0.f;
    #pragma unroll 8
    for (int i = 0; i < 64; i++) {
        sl += __half2float(g_f0[baseL + i * 128 + t]);
        sr += __half2float(g_f0[baseR + i * 128 + t]);
    }
    float v = sl * sr;
    #pragma unroll
    for (int o = 16; o > 0; o >>= 1) v += __shfl_down_sync(0xffffffffu, v, o);
    __shared__ float red[4];
    if ((t & 31) == 0) red[t >> 5] = v;
    __syncthreads();
    if (t == 0)
        logits[b] = (red[0] + red[1] + red[2] + red[3]) *
                    (1.f / (4096.f * SCALE * SCALE)) + out_bias[0];
}

// ---------------------------------------------------------------------------
extern "C" void kernel_launch(void* const* d_in, const int* in_sizes, int n_in,
                              void* d_out, int out_size) {
    const int*   node_idx  = (const int*)  d_in[0];
    const int*   neighbors = (const int*)  d_in[1];
    const float* emb       = (const float*)d_in[3];
    const float* W0        = (const float*)d_in[4];
    const float* b0        = (const float*)d_in[5];
    const float* W1        = (const float*)d_in[6];
    const float* b1        = (const float*)d_in[7];
    const float* out_bias  = (const float*)d_in[8];
    float* logits = (float*)d_out;

    cudaFuncSetAttribute(layer_k, cudaFuncAttributeMaxDynamicSharedMemorySize, SMEM_BYTES);

    {
        int total = NUM_LAYERS * 10 * 8192;
        prep_w<<<(total + 255) / 256, 256>>>(W0, W1);
    }
    {
        int total = N_NODES * 32;
        embed_k<<<(total + 255) / 256, 256>>>(node_idx, emb);
    }
    for (int l = 0; l < NUM_LAYERS; l++) {
        layer_k<<<NUM_TILES, 256, SMEM_BYTES>>>(
            l, l & 1, neighbors,
            b0 + (size_t)l * 128,
            b1 + (size_t)l * 128);
    }
    readout_k<<<NUM_EQ, 128>>>(out_bias, logits);
}

// round 8
// speedup vs baseline: 1.4990x; 1.4990x over previous
#include <cuda_runtime.h>
#include <cuda_fp16.h>
#include <cstdint>

#define N_NODES   131072
#define NUM_LAYERS 4
#define NUM_EQ    1024
#define NUM_TILES 1024
#define SCALE 64.0f

// tile geometry: pitch-144 rows (128B data + 16B gap) -> conflict-free ldmatrix
#define PITCH    144
#define AREG     18432              // 128 rows * 144
#define STAGE    36864              // A region + B region
#define STAGE_TX 34816u             // bytes per stage: 16384 (A) + 18432 (B)

// smem: [0..2048) neighbor ids, [2048..2088) 5 mbarriers, [4096..) 3 stage bufs
#define SMEM_BYTES (4096 + 3 * STAGE)

// ---------------- static device buffers (no allocs allowed) ----------------
__device__ __align__(16) __half g_f0[N_NODES * 128];
__device__ __align__(16) __half g_f1[N_NODES * 128];
__device__ __align__(128) unsigned char g_zero[128];   // zero-init pad-node row
// weight blob images: [layer][sub 0..9] x 18432B, pitch-144 smem image
// sub 0..7 -> W0 K-chunks (K=512), sub 8..9 -> W1 K-chunks (K=128)
__device__ __align__(16) unsigned char g_wblob[NUM_LAYERS * 10 * AREG];

// ---------------- helpers ----------------
__device__ __forceinline__ uint32_t smem_u32(const void* p) {
    uint32_t a;
    asm("{ .reg .u64 t; cvta.to.shared.u64 t, %1; cvt.u32.u64 %0, t; }"
        : "=r"(a) : "l"(p));
    return a;
}
#define MBARRIER_INIT(addr, cnt) \
    asm volatile("mbarrier.init.shared.b64 [%0], %1;" :: "r"(addr), "r"(cnt) : "memory")
#define MBARRIER_EXPECT_TX(addr, bytes) \
    asm volatile("mbarrier.arrive.expect_tx.shared.b64 _, [%0], %1;" \
                 :: "r"(addr), "r"(bytes) : "memory")
#define MBARRIER_WAIT_PARITY(addr, par) do {                                      \
    uint32_t _m = (uint32_t)(addr); uint32_t _p = (uint32_t)(par); uint32_t _d;   \
    asm volatile("{ .reg .pred p;"                                                \
        " mbarrier.try_wait.parity.acquire.cta.shared::cta.b64 p, [%1], %2;"      \
        " selp.b32 %0, 1, 0, p; }" : "=r"(_d) : "r"(_m), "r"(_p) : "memory");     \
    if (!_d) {                                                                    \
        asm volatile("{ .reg .pred P1;"                                           \
        " WL_%=:"                                                                 \
        " mbarrier.try_wait.parity.acquire.cta.shared::cta.b64 P1, [%0], %1, 0x989680;" \
        " @P1 bra.uni WD_%=;"                                                     \
        " bra.uni WL_%=;"                                                         \
        " WD_%=: }" :: "r"(_m), "r"(_p) : "memory");                              \
    }                                                                             \
} while (0)
#define BULK_G2S(dst, src, sz, mbar) \
    asm volatile("cp.async.bulk.shared::cluster.global.mbarrier::complete_tx::bytes " \
                 "[%0], [%1], %2, [%3];" \
                 :: "r"(dst), "l"(src), "r"(sz), "r"(mbar) : "memory")

__device__ __forceinline__ void ldsm4(uint32_t* r, uint32_t addr) {
    asm volatile("ldmatrix.sync.aligned.m8n8.x4.shared.b16 {%0,%1,%2,%3}, [%4];"
                 : "=r"(r[0]), "=r"(r[1]), "=r"(r[2]), "=r"(r[3]) : "r"(addr));
}
__device__ __forceinline__ void hmma(float* d, const uint32_t* a,
                                     uint32_t b0, uint32_t b1) {
    asm volatile(
        "mma.sync.aligned.m16n8k16.row.col.f32.f16.f16.f32 "
        "{%0,%1,%2,%3}, {%4,%5,%6,%7}, {%8,%9}, {%0,%1,%2,%3};"
        : "+f"(d[0]), "+f"(d[1]), "+f"(d[2]), "+f"(d[3])
        : "r"(a[0]), "r"(a[1]), "r"(a[2]), "r"(a[3]), "r"(b0), "r"(b1));
}

// ---------------------------------------------------------------------------
// prep: transposed fp16 weight blob images (pitch-144, bulk-copy ready)
// ---------------------------------------------------------------------------
__global__ void prep_w(const float* __restrict__ W0, const float* __restrict__ W1) {
    int i = blockIdx.x * blockDim.x + threadIdx.x;
    if (i >= NUM_LAYERS * 10 * 128 * 64) return;
    int kk  = i & 63;             // K within subtile
    int n   = (i >> 6) & 127;     // N row 0..127
    int g   = i >> 13;            // l*10 + sub
    int sub = g % 10;
    int l   = g / 10;
    float w;
    if (sub < 8) w = W0[((size_t)l * 512 + sub * 64 + kk) * 128 + n];
    else         w = W1[((size_t)l * 128 + (sub - 8) * 64 + kk) * 128 + n];
    *reinterpret_cast<__half*>(
        g_wblob + (size_t)g * AREG + n * PITCH + kk * 2) = __float2half_rn(w);
}

// ---------------------------------------------------------------------------
// embed: feats = SCALE * emb[node_idx]  -> fp16 into buffer 0
// ---------------------------------------------------------------------------
__global__ void embed_k(const int* __restrict__ node_idx, const float* __restrict__ emb) {
    int i = blockIdx.x * blockDim.x + threadIdx.x;   // one per 4 elems
    if (i >= N_NODES * 32) return;
    int n  = i >> 5;
    int c4 = i & 31;
    float4 vv = reinterpret_cast<const float4*>(emb)[node_idx[n] * 32 + c4];
    __half2 p0 = __floats2half2_rn(vv.x * SCALE, vv.y * SCALE);
    __half2 p1 = __floats2half2_rn(vv.z * SCALE, vv.w * SCALE);
    reinterpret_cast<uint2*>(g_f0)[i] =
        make_uint2(*reinterpret_cast<uint32_t*>(&p0), *reinterpret_cast<uint32_t*>(&p1));
}

// ---------------------------------------------------------------------------
// fused layer: fp16 HMMA, cp.async.bulk (TMA-engine) loads, ring-3
// ---------------------------------------------------------------------------
__device__ __forceinline__ void compute64(float acc[2][8][4], uint32_t buf,
                                          int lane, int wy, int wx) {
    const int rsel = lane & 15;
    const int hi   = lane >> 4;
    const uint32_t abase = buf + (wy * 32 + rsel) * PITCH;
    const uint32_t bbase = buf + AREG + (wx * 64 + rsel) * PITCH;
    #pragma unroll
    for (int ks = 0; ks < 4; ks++) {
        const uint32_t co = (uint32_t)(2 * ks + hi) << 4;
        uint32_t a[2][4];
        #pragma unroll
        for (int mi = 0; mi < 2; mi++)
            ldsm4(a[mi], abase + mi * (16 * PITCH) + co);
        #pragma unroll
        for (int g = 0; g < 4; g++) {
            uint32_t b[4];
            ldsm4(b, bbase + g * (16 * PITCH) + co);
            #pragma unroll
            for (int mi = 0; mi < 2; mi++) {
                hmma(acc[mi][2 * g],     a[mi], b[0], b[2]);
                hmma(acc[mi][2 * g + 1], a[mi], b[1], b[3]);
            }
        }
    }
}

__global__ __launch_bounds__(256, 2)
void layer_k(int l, int srcBuf, const int* __restrict__ neighbors,
             const float* __restrict__ b0, const float* __restrict__ b1) {
    extern __shared__ __align__(128) char smem[];
    int* sNbr = (int*)smem;
    const uint32_t sb   = smem_u32(smem);
    const uint32_t MBAR = sb + 2048;     // 3 stage mbars + 2 W1 mbars (8B each)
    const uint32_t BUF  = sb + 4096;

    const int tid = threadIdx.x, lane = tid & 31, wid = tid >> 5;
    const int wy = wid >> 1, wx = wid & 1;

    const __half* fin = srcBuf ? g_f1 : g_f0;
    __half* fout      = srcBuf ? g_f0 : g_f1;

    sNbr[tid]       = neighbors[blockIdx.x * 512 + tid];
    sNbr[tid + 256] = neighbors[blockIdx.x * 512 + 256 + tid];
    if (tid == 0) {
        MBARRIER_INIT(MBAR + 0, 1);
        MBARRIER_INIT(MBAR + 8, 1);
        MBARRIER_INIT(MBAR + 16, 1);
        MBARRIER_INIT(MBAR + 24, 1);   // W1 sub8
        MBARRIER_INIT(MBAR + 32, 1);   // W1 sub9
    }
    __syncthreads();

    const char* finB = reinterpret_cast<const char*>(fin);

    // issue one K=64 gather stage via bulk copies (lane 0 of each warp)
    auto issueStage = [&](int s) {
        const uint32_t buf  = BUF + (s % 3) * STAGE;
        const uint32_t mbar = MBAR + (s % 3) * 8;
        const int j = s >> 1, half = s & 1;
        if (wid == 0) {
            MBARRIER_EXPECT_TX(mbar, STAGE_TX);
            BULK_G2S(buf + AREG,
                     g_wblob + (size_t)(l * 10 + s) * AREG, (uint32_t)AREG, mbar);
        }
        #pragma unroll
        for (int r = 0; r < 16; r++) {
            int row = wid * 16 + r;
            int sn = sNbr[row * 4 + j];
            const char* src = (sn == N_NODES)
                ? (const char*)g_zero
                : finB + (size_t)sn * 256 + half * 128;
            BULK_G2S(buf + row * PITCH, src, 128u, mbar);
        }
    };
    // W1 prefetch on dedicated mbarriers (single phase each, wait parity 0)
    // q=0: sub8 -> buf2.B (mbar+24); q=1: sub9 -> buf0.B (mbar+32)
    auto issueW1 = [&](int q) {
        if (wid == 0) {
            const uint32_t buf  = BUF + (q ? 0 : 2) * STAGE;
            const uint32_t mbar = MBAR + 24 + q * 8;
            MBARRIER_EXPECT_TX(mbar, (uint32_t)AREG);
            BULK_G2S(buf + AREG,
                     g_wblob + (size_t)(l * 10 + 8 + q) * AREG, (uint32_t)AREG, mbar);
        }
    };

    float acc[2][8][4];
    #pragma unroll
    for (int mi = 0; mi < 2; mi++)
        #pragma unroll
        for (int ni = 0; ni < 8; ni++)
            #pragma unroll
            for (int q = 0; q < 4; q++) acc[mi][ni][q] = 0.f;

    // -------- GEMM1: gathered[128x512] @ W0, 8 K=64 stages, ring-3 --------
    if (lane == 0) { issueStage(0); issueStage(1); }
    #pragma unroll 1
    for (int s = 0; s < 8; s++) {
        __syncthreads();                 // all warps done compute(s-1) -> buf (s+2)%3 free
        if (lane == 0) {
            if (s < 6)      issueStage(s + 2);
            else            issueW1(s - 6);      // s=6: sub8->buf2.B, s=7: sub9->buf0.B
        }
        MBARRIER_WAIT_PARITY(MBAR + (s % 3) * 8, (s / 3) & 1);
        compute64(acc, BUF + (s % 3) * STAGE, lane, wy, wx);
    }
    __syncthreads();                     // all computes done; buf0.A/buf2.A free for H

    // -------- epilogue1: H = relu(acc + s*b0) -> fp16 into A regions ----
    // wx=0 warps produce GEMM2-K 0..63  -> buf2.A (pairs with W1 sub8 in buf2.B)
    // wx=1 warps produce GEMM2-K 64..127-> buf0.A (pairs with W1 sub9 in buf0.B)
    const uint32_t hbuf = wx ? (BUF + 0 * STAGE) : (BUF + 2 * STAGE);
    #pragma unroll
    for (int mi = 0; mi < 2; mi++) {
        #pragma unroll
        for (int ni = 0; ni < 8; ni++) {
            int kl = ni * 8 + (lane & 3) * 2;      // k within GEMM2 subtile
            int ncol = wx * 64 + kl;               // GEMM1 output column
            float bb0 = __ldg(&b0[ncol]) * SCALE;
            float bb1 = __ldg(&b0[ncol + 1]) * SCALE;
            #pragma unroll
            for (int h = 0; h < 2; h++) {          // row halves
                int row = wy * 32 + mi * 16 + (lane >> 2) + h * 8;
                float x0 = acc[mi][ni][2 * h]     + bb0;
                float x1 = acc[mi][ni][2 * h + 1] + bb1;
                x0 = x0 > 0.f ? x0 : 0.f;
                x1 = x1 > 0.f ? x1 : 0.f;
                __half2 p = __floats2half2_rn(x0, x1);
                uint32_t a = hbuf + row * PITCH + kl * 2;
                asm volatile("st.shared.b32 [%0], %1;"
                             :: "r"(a), "r"(*reinterpret_cast<uint32_t*>(&p)) : "memory");
            }
        }
    }
    __syncthreads();                     // H visible to all warps

    // -------- GEMM2: H[128x128] @ W1, 2 K=64 stages --------
    #pragma unroll
    for (int mi = 0; mi < 2; mi++)
        #pragma unroll
        for (int ni = 0; ni < 8; ni++)
            #pragma unroll
            for (int q = 0; q < 4; q++) acc[mi][ni][q] = 0.f;
    MBARRIER_WAIT_PARITY(MBAR + 24, 0);  // W1 sub8 ready in buf2.B
    compute64(acc, BUF + 2 * STAGE, lane, wy, wx);
    MBARRIER_WAIT_PARITY(MBAR + 32, 0);  // W1 sub9 ready in buf0.B
    compute64(acc, BUF + 0 * STAGE, lane, wy, wx);

    // -------- epilogue2: out = acc + s*b1 -> fp16 to global --------
    #pragma unroll
    for (int mi = 0; mi < 2; mi++) {
        #pragma unroll
        for (int ni = 0; ni < 8; ni++) {
            int ncol = wx * 64 + ni * 8 + (lane & 3) * 2;
            float bb0 = __ldg(&b1[ncol]) * SCALE;
            float bb1 = __ldg(&b1[ncol + 1]) * SCALE;
            #pragma unroll
            for (int h = 0; h < 2; h++) {
                int row = wy * 32 + mi * 16 + (lane >> 2) + h * 8;
                size_t gOff = (size_t)(blockIdx.x * 128 + row) * 128 + ncol;
                __half2 p = __floats2half2_rn(acc[mi][ni][2 * h] + bb0,
                                              acc[mi][ni][2 * h + 1] + bb1);
                *reinterpret_cast<uint32_t*>(fout + gOff) =
                    *reinterpret_cast<uint32_t*>(&p);
            }
        }
    }
}

// ---------------------------------------------------------------------------
// readout: logits[b] = dot(meanL, meanR)/s^2 + out_bias  (feats in g_f0)
// ---------------------------------------------------------------------------
__global__ void readout_k(const float* __restrict__ out_bias, float* __restrict__ logits) {
    const int b = blockIdx.x;
    const int t = threadIdx.x;   // 0..127
    size_t baseL = (size_t)(2 * b) * 64 * 128;
    size_t baseR = baseL + 64 * 128;
    float sl = 0.f, sr = 0.f;
    #pragma unroll 8
    for (int i = 0; i < 64; i++) {
        sl += __half2float(g_f0[baseL + i * 128 + t]);
        sr += __half2float(g_f0[baseR + i * 128 + t]);
    }
    float v = sl * sr;
    #pragma unroll
    for (int o = 16; o > 0; o >>= 1) v += __shfl_down_sync(0xffffffffu, v, o);
    __shared__ float red[4];
    if ((t & 31) == 0) red[t >> 5] = v;
    __syncthreads();
    if (t == 0)
        logits[b] = (red[0] + red[1] + red[2] + red[3]) *
                    (1.f / (4096.f * SCALE * SCALE)) + out_bias[0];
}

// ---------------------------------------------------------------------------
extern "C" void kernel_launch(void* const* d_in, const int* in_sizes, int n_in,
                              void* d_out, int out_size) {
    const int*   node_idx  = (const int*)  d_in[0];
    const int*   neighbors = (const int*)  d_in[1];
    const float* emb       = (const float*)d_in[3];
    const float* W0        = (const float*)d_in[4];
    const float* b0        = (const float*)d_in[5];
    const float* W1        = (const float*)d_in[6];
    const float* b1        = (const float*)d_in[7];
    const float* out_bias  = (const float*)d_in[8];
    float* logits = (float*)d_out;

    cudaFuncSetAttribute(layer_k, cudaFuncAttributeMaxDynamicSharedMemorySize, SMEM_BYTES);

    {
        int total = NUM_LAYERS * 10 * 128 * 64;
        prep_w<<<(total + 255) / 256, 256>>>(W0, W1);
    }
    {
        int total = N_NODES * 32;
        embed_k<<<(total + 255) / 256, 256>>>(node_idx, emb);
    }
    for (int l = 0; l < NUM_LAYERS; l++) {
        layer_k<<<NUM_TILES, 256, SMEM_BYTES>>>(
            l, l & 1, neighbors,
            b0 + (size_t)l * 128,
            b1 + (size_t)l * 128);
    }
    readout_k<<<NUM_EQ, 128>>>(out_bias, logits);
}

// round 9
// speedup vs baseline: 1.9298x; 1.2874x over previous
#include <cuda_runtime.h>
#include <cuda_fp16.h>
#include <cstdint>

#define N_NODES   131072
#define NUM_LAYERS 4
#define NUM_EQ    1024
#define NUM_TILES 1024
#define SCALE 64.0f

// smem: [0..2048) neighbor ids, [4096 ..) 3 x 16KB A-stage bufs
#define SMEM_BYTES (4096 + 3 * 16384)

// ---------------- static device buffers (no allocs allowed) ----------------
__device__ __align__(16) __half g_f0[N_NODES * 128];
__device__ __align__(16) __half g_f1[N_NODES * 128];
// W fragments: word i <-> (l, sub, wx, ks, g, lane, w); one LDG.128/(ks,g)/lane
// sub 0..7 -> W0 K-chunks (K=512), sub 8..9 -> W1 K-chunks (K=128)
__device__ __align__(16) uint4 g_wfrag[NUM_LAYERS * 10 * 2 * 512];

// ---------------- helpers ----------------
__device__ __forceinline__ uint32_t smem_u32(const void* p) {
    uint32_t a;
    asm("{ .reg .u64 t; cvta.to.shared.u64 t, %1; cvt.u32.u64 %0, t; }"
        : "=r"(a) : "l"(p));
    return a;
}
#define CP16(dst, src, sz) \
    asm volatile("cp.async.cg.shared.global [%0], [%1], 16, %2;" \
                 :: "r"(dst), "l"(src), "r"(sz) : "memory")
#define CPCOMMIT() asm volatile("cp.async.commit_group;" ::: "memory")
#define CPWAIT0()  asm volatile("cp.async.wait_group 0;" ::: "memory")
#define CPWAIT1()  asm volatile("cp.async.wait_group 1;" ::: "memory")

__device__ __forceinline__ void ldsm4(uint32_t* r, uint32_t addr) {
    asm volatile("ldmatrix.sync.aligned.m8n8.x4.shared.b16 {%0,%1,%2,%3}, [%4];"
                 : "=r"(r[0]), "=r"(r[1]), "=r"(r[2]), "=r"(r[3]) : "r"(addr));
}
__device__ __forceinline__ void hmma(float* d, const uint32_t* a,
                                     uint32_t b0, uint32_t b1) {
    asm volatile(
        "mma.sync.aligned.m16n8k16.row.col.f32.f16.f16.f32 "
        "{%0,%1,%2,%3}, {%4,%5,%6,%7}, {%8,%9}, {%0,%1,%2,%3};"
        : "+f"(d[0]), "+f"(d[1]), "+f"(d[2]), "+f"(d[3])
        : "r"(a[0]), "r"(a[1]), "r"(a[2]), "r"(a[3]), "r"(b0), "r"(b1));
}
// A tile: 128 rows x 64 k fp16 (128B rows, 8x16B chunks), XOR swizzle for ldsm
__device__ __forceinline__ uint32_t tadr(uint32_t base, int row, int ck) {
    return base + row * 128 + (((uint32_t)ck ^ (row & 7)) << 4);
}

// ---------------------------------------------------------------------------
// prep: weights -> per-lane mma fragment order.
// word i = ((((((l*10+s)*2+wx)*4+ks)*4+g)*32+lane)*4+w), value = half2
//   n = wx*64 + g*16 + (w>>1)*8 + (lane>>2)
//   k = ks*16 + (w&1)*8 + (lane&3)*2   (within sub; pair k, k+1)
// ---------------------------------------------------------------------------
__global__ void prep_w(const float* __restrict__ W0, const float* __restrict__ W1) {
    int i = blockIdx.x * blockDim.x + threadIdx.x;
    if (i >= NUM_LAYERS * 10 * 2 * 2048) return;
    int w    = i & 3;
    int lane = (i >> 2) & 31;
    int g    = (i >> 7) & 3;
    int ks   = (i >> 9) & 3;
    int wx   = (i >> 11) & 1;
    int rest = i >> 12;
    int s    = rest % 10;
    int l    = rest / 10;
    int n = wx * 64 + g * 16 + ((w >> 1) << 3) + (lane >> 2);
    int k = ks * 16 + ((w & 1) << 3) + (lane & 3) * 2;
    float w0, w1;
    if (s < 8) {
        const float* base = W0 + ((size_t)l * 512 + s * 64 + k) * 128 + n;
        w0 = base[0]; w1 = base[128];
    } else {
        const float* base = W1 + ((size_t)l * 128 + (s - 8) * 64 + k) * 128 + n;
        w0 = base[0]; w1 = base[128];
    }
    __half2 p = __floats2half2_rn(w0, w1);
    reinterpret_cast<uint32_t*>(g_wfrag)[i] = *reinterpret_cast<uint32_t*>(&p);
}

// ---------------------------------------------------------------------------
// embed: feats = SCALE * emb[node_idx]  -> fp16 into buffer 0
// ---------------------------------------------------------------------------
__global__ void embed_k(const int* __restrict__ node_idx, const float* __restrict__ emb) {
    int i = blockIdx.x * blockDim.x + threadIdx.x;   // one per 4 elems
    if (i >= N_NODES * 32) return;
    int n  = i >> 5;
    int c4 = i & 31;
    float4 vv = reinterpret_cast<const float4*>(emb)[node_idx[n] * 32 + c4];
    __half2 p0 = __floats2half2_rn(vv.x * SCALE, vv.y * SCALE);
    __half2 p1 = __floats2half2_rn(vv.z * SCALE, vv.w * SCALE);
    reinterpret_cast<uint2*>(g_f0)[i] =
        make_uint2(*reinterpret_cast<uint32_t*>(&p0), *reinterpret_cast<uint32_t*>(&p1));
}

// ---------------------------------------------------------------------------
// fused layer: fp16 HMMA, A staged via cp.async ring-3, B straight from
// global fragment blobs (coalesced LDG.128, L1-broadcast across warps)
// ---------------------------------------------------------------------------
__device__ __forceinline__ void compute64(float acc[2][8][4], uint32_t bufA,
                                          const uint4* __restrict__ wsub,
                                          int lane, int wy) {
    const int rsel = lane & 15;
    const int hi   = lane >> 4;
    #pragma unroll
    for (int ks = 0; ks < 4; ks++) {
        uint32_t a[2][4];
        #pragma unroll
        for (int mi = 0; mi < 2; mi++)
            ldsm4(a[mi], tadr(bufA, wy * 32 + mi * 16 + rsel, 2 * ks + hi));
        #pragma unroll
        for (int g = 0; g < 4; g++) {
            uint4 q = wsub[(ks * 4 + g) * 32 + lane];
            #pragma unroll
            for (int mi = 0; mi < 2; mi++) {
                hmma(acc[mi][2 * g],     a[mi], q.x, q.y);
                hmma(acc[mi][2 * g + 1], a[mi], q.z, q.w);
            }
        }
    }
}

__global__ __launch_bounds__(256, 2)
void layer_k(int l, int srcBuf, const int* __restrict__ neighbors,
             const float* __restrict__ b0, const float* __restrict__ b1) {
    extern __shared__ __align__(16) char smem[];
    int* sNbr = (int*)smem;
    const uint32_t sb = smem_u32(smem);
    const uint32_t BUF0 = sb + 4096, BUF1 = BUF0 + 16384;

    const int tid = threadIdx.x, lane = tid & 31, wid = tid >> 5;
    const int wy = wid >> 1, wx = wid & 1;

    const __half* fin = srcBuf ? g_f1 : g_f0;
    __half* fout      = srcBuf ? g_f0 : g_f1;

    sNbr[tid]       = neighbors[blockIdx.x * 512 + tid];
    sNbr[tid + 256] = neighbors[blockIdx.x * 512 + 256 + tid];
    __syncthreads();

    const char* finB = reinterpret_cast<const char*>(fin);
    // fragment region for (sub s, this warp's wx): 512 uint4
    const uint4* wbase = g_wfrag + (size_t)(l * 10) * 1024 + wx * 512;

    // one K=64 stage: A gather only (zfill for pad node), 4 cp.async/thread
    auto issue = [&](int s) {
        const uint32_t buf = BUF0 + (s % 3) * 16384;
        const int j = s >> 1, half = s & 1;
        #pragma unroll
        for (int r = 0; r < 4; r++) {
            int c = tid + 256 * r;                 // 0..1023
            int row = c >> 3, ck = c & 7;
            int sn = sNbr[row * 4 + j];
            uint32_t sz = (sn == N_NODES) ? 0u : 16u;
            size_t so = (size_t)sn * 256 + half * 128 + ck * 16;
            CP16(tadr(buf, row, ck), finB + so, sz);
        }
    };

    float acc[2][8][4];
    #pragma unroll
    for (int mi = 0; mi < 2; mi++)
        #pragma unroll
        for (int ni = 0; ni < 8; ni++)
            #pragma unroll
            for (int q = 0; q < 4; q++) acc[mi][ni][q] = 0.f;

    // -------- GEMM1: gathered[128x512] @ W0, 8 K=64 stages, ring-3 --------
    issue(0); CPCOMMIT();
    issue(1); CPCOMMIT();
    #pragma unroll 1
    for (int s = 0; s < 8; s++) {
        if (s < 7) { CPWAIT1(); } else { CPWAIT0(); }
        __syncthreads();                 // stage s visible; compute(s-1) done
        if (s < 6) { issue(s + 2); CPCOMMIT(); }   // writes buf (s-1)%3, now free
        compute64(acc, BUF0 + (s % 3) * 16384, wbase + (size_t)s * 1024, lane, wy);
    }
    __syncthreads();                     // all warps done reading buf0/buf1

    // -------- epilogue1: H = relu(acc + s*b0) -> fp16 A tiles (buf0/buf1) ----
    const uint32_t hbuf = wx ? BUF1 : BUF0;        // wx=0 -> k 0..63, wx=1 -> 64..127
    #pragma unroll
    for (int mi = 0; mi < 2; mi++) {
        #pragma unroll
        for (int ni = 0; ni < 8; ni++) {
            int kl = ni * 8 + (lane & 3) * 2;      // k within GEMM2 subtile
            int ncol = wx * 64 + kl;               // GEMM1 output column
            float bb0 = __ldg(&b0[ncol]) * SCALE;
            float bb1 = __ldg(&b0[ncol + 1]) * SCALE;
            #pragma unroll
            for (int h = 0; h < 2; h++) {          // row halves
                int row = wy * 32 + mi * 16 + (lane >> 2) + h * 8;
                float x0 = acc[mi][ni][2 * h]     + bb0;
                float x1 = acc[mi][ni][2 * h + 1] + bb1;
                x0 = x0 > 0.f ? x0 : 0.f;
                x1 = x1 > 0.f ? x1 : 0.f;
                __half2 p = __floats2half2_rn(x0, x1);
                uint32_t a = tadr(hbuf, row, kl >> 3) + (kl & 7) * 2;
                asm volatile("st.shared.b32 [%0], %1;"
                             :: "r"(a), "r"(*reinterpret_cast<uint32_t*>(&p)) : "memory");
            }
        }
    }
    __syncthreads();                     // H visible to all warps

    // -------- GEMM2: H[128x128] @ W1 (subs 8,9), B from registers --------
    #pragma unroll
    for (int mi = 0; mi < 2; mi++)
        #pragma unroll
        for (int ni = 0; ni < 8; ni++)
            #pragma unroll
            for (int q = 0; q < 4; q++) acc[mi][ni][q] = 0.f;
    compute64(acc, BUF0, wbase + (size_t)8 * 1024, lane, wy);
    compute64(acc, BUF1, wbase + (size_t)9 * 1024, lane, wy);

    // -------- epilogue2: out = acc + s*b1 -> fp16 to global --------
    #pragma unroll
    for (int mi = 0; mi < 2; mi++) {
        #pragma unroll
        for (int ni = 0; ni < 8; ni++) {
            int ncol = wx * 64 + ni * 8 + (lane & 3) * 2;
            float bb0 = __ldg(&b1[ncol]) * SCALE;
            float bb1 = __ldg(&b1[ncol + 1]) * SCALE;
            #pragma unroll
            for (int h = 0; h < 2; h++) {
                int row = wy * 32 + mi * 16 + (lane >> 2) + h * 8;
                size_t gOff = (size_t)(blockIdx.x * 128 + row) * 128 + ncol;
                __half2 p = __floats2half2_rn(acc[mi][ni][2 * h] + bb0,
                                              acc[mi][ni][2 * h + 1] + bb1);
                *reinterpret_cast<uint32_t*>(fout + gOff) =
                    *reinterpret_cast<uint32_t*>(&p);
            }
        }
    }
}

// ---------------------------------------------------------------------------
// readout: logits[b] = dot(meanL, meanR)/s^2 + out_bias  (feats in g_f0)
// ---------------------------------------------------------------------------
__global__ void readout_k(const float* __restrict__ out_bias, float* __restrict__ logits) {
    const int b = blockIdx.x;
    const int t = threadIdx.x;   // 0..127
    size_t baseL = (size_t)(2 * b) * 64 * 128;
    size_t baseR = baseL + 64 * 128;
    float sl = 0.f, sr = 0.f;
    #pragma unroll 8
    for (int i = 0; i < 64; i++) {
        sl += __half2float(g_f0[baseL + i * 128 + t]);
        sr += __half2float(g_f0[baseR + i * 128 + t]);
    }
    float v = sl * sr;
    #pragma unroll
    for (int o = 16; o > 0; o >>= 1) v += __shfl_down_sync(0xffffffffu, v, o);
    __shared__ float red[4];
    if ((t & 31) == 0) red[t >> 5] = v;
    __syncthreads();
    if (t == 0)
        logits[b] = (red[0] + red[1] + red[2] + red[3]) *
                    (1.f / (4096.f * SCALE * SCALE)) + out_bias[0];
}

// ---------------------------------------------------------------------------
extern "C" void kernel_launch(void* const* d_in, const int* in_sizes, int n_in,
                              void* d_out, int out_size) {
    const int*   node_idx  = (const int*)  d_in[0];
    const int*   neighbors = (const int*)  d_in[1];
    const float* emb       = (const float*)d_in[3];
    const float* W0        = (const float*)d_in[4];
    const float* b0        = (const float*)d_in[5];
    const float* W1        = (const float*)d_in[6];
    const float* b1        = (const float*)d_in[7];
    const float* out_bias  = (const float*)d_in[8];
    float* logits = (float*)d_out;

    cudaFuncSetAttribute(layer_k, cudaFuncAttributeMaxDynamicSharedMemorySize, SMEM_BYTES);

    {
        int total = NUM_LAYERS * 10 * 2 * 2048;
        prep_w<<<(total + 255) / 256, 256>>>(W0, W1);
    }
    {
        int total = N_NODES * 32;
        embed_k<<<(total + 255) / 256, 256>>>(node_idx, emb);
    }
    for (int l = 0; l < NUM_LAYERS; l++) {
        layer_k<<<NUM_TILES, 256, SMEM_BYTES>>>(
            l, l & 1, neighbors,
            b0 + (size_t)l * 128,
            b1 + (size_t)l * 128);
    }
    readout_k<<<NUM_EQ, 128>>>(out_bias, logits);
}